// round 12
// baseline (speedup 1.0000x reference)
#include <cuda_runtime.h>
#include <cstdint>

// assignments [512, 8192] int32 -> frequency [512, 50257] float32.
#define VOCAB   50257
#define SEQ     8192
#define THREADS 1024

// Global reduce-add, no return value -> SASS REDG (fire-and-forget).
__device__ __forceinline__ void red_add_f32(float* p, float v) {
    asm volatile("red.global.add.f32 [%0], %1;" :: "l"(p), "f"(v) : "memory");
}

// One CTA per row. Phase 1: zero the row's output slice (the compulsory
// 201 KB write, done as float4 STGs). Phase 2: REDG.ADD inv=2^-13 into
// out[b][token] per token. All partial sums are k*2^-13 (k<=8192) -> exact
// in fp32, and the row sum is exactly 8192 so no normalization pass needed.
// REDG spread-addr issues at 1.29 cyc/lane vs smem ATOMS' 2 cyc/lane -> this
// trades the smem-atomic floor (~26us) for the REDG floor (~17us). The row
// is L2-resident (just written by this CTA) so the RMWs hit L2.
__global__ __launch_bounds__(THREADS, 2)
void XTermFrequency_redg_kernel(const int* __restrict__ assign,
                                float* __restrict__ out) {
    const int b   = blockIdx.x;
    const int tid = threadIdx.x;

    float* __restrict__ orow = out + (size_t)b * VOCAB;

    // ---- Phase 1: zero this row (alignment-safe float4 body) ----
    // Row byte offset = b * 201028; 201028 % 16 == 4, so alignment varies
    // with b. Peel to a 16B boundary, vector body, scalar tail.
    const int head = (int)(((16u - ((uint32_t)(uintptr_t)orow & 15u)) & 15u) >> 2);
    for (int i = tid; i < head; i += THREADS) {
        orow[i] = 0.0f;
    }
    const int n4 = (VOCAB - head) >> 2;           // float4 count
    float4* __restrict__ o4 = reinterpret_cast<float4*>(orow + head);
    const float4 z4 = make_float4(0.f, 0.f, 0.f, 0.f);
    for (int i = tid; i < n4; i += THREADS) {
        o4[i] = z4;
    }
    for (int i = head + (n4 << 2) + tid; i < VOCAB; i += THREADS) {
        orow[i] = 0.0f;
    }

    // CTA-scope ordering: all zeros visible before this CTA's atomics.
    __syncthreads();

    // ---- Phase 2: scatter-add 1/SEQ per token (REDG, no return) ----
    const float inv = 1.0f / (float)SEQ;          // 2^-13, exact
    const int4* __restrict__ row =
        reinterpret_cast<const int4*>(assign + (size_t)b * SEQ);
    #pragma unroll
    for (int i = tid; i < SEQ / 4; i += THREADS) {
        const int4 v = row[i];
        red_add_f32(orow + v.x, inv);
        red_add_f32(orow + v.y, inv);
        red_add_f32(orow + v.z, inv);
        red_add_f32(orow + v.w, inv);
    }
}

extern "C" void kernel_launch(void* const* d_in, const int* in_sizes, int n_in,
                              void* d_out, int out_size) {
    const int* assign = (const int*)d_in[0];   // [batch, SEQ] int32
    float*     out    = (float*)d_out;         // [batch, VOCAB] float32

    const int batch = in_sizes[0] / SEQ;       // 512

    XTermFrequency_redg_kernel<<<batch, THREADS>>>(assign, out);
}

// round 13
// speedup vs baseline: 1.1860x; 1.1860x over previous
#include <cuda_runtime.h>
#include <cstdint>

// assignments [512, 8192] int32 -> frequency [512, 50257] float32.
#define VOCAB   50257
#define SEQ     8192
#define THREADS 1024

// Vocab split point: bins [0, T) go through the L2 atomic path (REDG into the
// output row, which this CTA zeroes first); bins [T, VOCAB) go through the
// shared-memory atomic path (packed u16 counters) and are written out with
// plain stores. T chosen so op counts match the measured relative capacity of
// the two backends (L2 path ~0.42, smem path ~0.58).
#define T_SPLIT 21100
#define HI_BINS (VOCAB - T_SPLIT)            // 29157
#define HI_WORDS ((HI_BINS + 1) / 2)         // 14579 packed words = 58.3 KB

__device__ __forceinline__ void red_add_f32(float* p, float v) {
    asm volatile("red.global.add.f32 [%0], %1;" :: "l"(p), "f"(v) : "memory");
}

__global__ __launch_bounds__(THREADS, 2)
void XTermFrequency_hybrid_kernel(const int* __restrict__ assign,
                                  float* __restrict__ out) {
    extern __shared__ unsigned int s_hist[];   // HI_WORDS packed u16 pairs

    const int b   = blockIdx.x;
    const int tid = threadIdx.x;
    const float inv = 1.0f / (float)SEQ;       // 2^-13, exact in fp32

    float* __restrict__ orow = out + (size_t)b * VOCAB;

    // ---- Phase 1a: zero the packed smem histogram ----
    for (int i = tid; i < HI_WORDS; i += THREADS) {
        s_hist[i] = 0u;
    }

    // ---- Phase 1b: zero the REDG target slice out[0 .. T_SPLIT) ----
    // Row base alignment varies with b (row stride 201028 B, %16 == 4):
    // peel to 16B, float4 body, scalar tail.
    {
        const int head =
            (int)(((16u - ((uint32_t)(uintptr_t)orow & 15u)) & 15u) >> 2);
        for (int i = tid; i < head; i += THREADS) {
            orow[i] = 0.0f;
        }
        const int n4 = (T_SPLIT - head) >> 2;
        float4* __restrict__ o4 = reinterpret_cast<float4*>(orow + head);
        const float4 z4 = make_float4(0.f, 0.f, 0.f, 0.f);
        for (int i = tid; i < n4; i += THREADS) {
            o4[i] = z4;
        }
        for (int i = head + (n4 << 2) + tid; i < T_SPLIT; i += THREADS) {
            orow[i] = 0.0f;
        }
    }

    // Release our zero-stores to L2 before any thread's REDGs can RMW them,
    // and order the smem zero before smem atomics.
    __threadfence();
    __syncthreads();

    // ---- Phase 2: token loop — both atomic backends in parallel ----
    const int4* __restrict__ row =
        reinterpret_cast<const int4*>(assign + (size_t)b * SEQ);
    #pragma unroll
    for (int i = tid; i < SEQ / 4; i += THREADS) {
        const int4 t = row[i];
        #pragma unroll
        for (int e = 0; e < 4; e++) {
            const int v = (e == 0) ? t.x : (e == 1) ? t.y : (e == 2) ? t.z : t.w;
            if (v < T_SPLIT) {
                red_add_f32(orow + v, inv);              // L2 atomic ALUs
            } else {
                const int r = v - T_SPLIT;               // smem atomic unit
                atomicAdd(&s_hist[r >> 1], 1u << ((r & 1) << 4));
            }
        }
    }
    __syncthreads();

    // ---- Phase 3: readout smem slice -> out[T_SPLIT .. VOCAB) (plain STG) ----
    for (int w = tid; w < HI_WORDS; w += THREADS) {
        const unsigned int c = s_hist[w];
        const int v = T_SPLIT + 2 * w;
        orow[v] = (float)(c & 0xFFFFu) * inv;
        if (v + 1 < VOCAB) {
            orow[v + 1] = (float)(c >> 16) * inv;
        }
    }
}

extern "C" void kernel_launch(void* const* d_in, const int* in_sizes, int n_in,
                              void* d_out, int out_size) {
    const int* assign = (const int*)d_in[0];   // [batch, SEQ] int32
    float*     out    = (float*)d_out;         // [batch, VOCAB] float32

    const int batch = in_sizes[0] / SEQ;       // 512
    const size_t smem_bytes = (size_t)HI_WORDS * sizeof(unsigned int); // 58.3 KB

    cudaFuncSetAttribute(XTermFrequency_hybrid_kernel,
                         cudaFuncAttributeMaxDynamicSharedMemorySize,
                         (int)smem_bytes);

    XTermFrequency_hybrid_kernel<<<batch, THREADS, smem_bytes>>>(assign, out);
}

// round 14
// speedup vs baseline: 1.3959x; 1.1770x over previous
#include <cuda_runtime.h>
#include <cstdint>

// assignments [512, 8192] int32 -> frequency [512, 50257] float32.
#define VOCAB   50257
#define WORDS   ((VOCAB + 1) / 2)   // 25129 packed words (2 x u16 counters)
#define SEQ     8192
#define THREADS 1024

// Packed-u16 smem histogram, one 32-bit ATOMS per token (counts <= 8192 < 2^16,
// low half can never carry into the high half). smem = 98.2 KB -> 2 CTAs/SM so
// aux phases (zero/readout/STG drain) of one CTA hide under the co-resident
// CTA's atomic phase. All scattered RMWs cost ~2 cyc/lane through the LSU
// regardless of backend (measured R5/R7/R11/R13), so the atomic phase is the
// fixed floor; this kernel minimizes everything around it.
__global__ __launch_bounds__(THREADS, 2)
void XTermFrequency_hist_kernel(const int* __restrict__ assign,
                                float* __restrict__ out) {
    extern __shared__ unsigned int s_hist[];

    const int b   = blockIdx.x;
    const int tid = threadIdx.x;

    // ---- Phase 1: zero packed histogram with STS.128 ----
    // 25129 words = 6282 uint4 + 1 trailing word.
    {
        uint4* __restrict__ s4 = reinterpret_cast<uint4*>(s_hist);
        const uint4 z = make_uint4(0u, 0u, 0u, 0u);
        #pragma unroll
        for (int i = tid; i < WORDS / 4; i += THREADS) {   // 6282
            s4[i] = z;
        }
        if (tid == 0) {
            s_hist[WORDS - 1] = 0u;                        // word 25128
        }
    }
    __syncthreads();

    // ---- Phase 2: histogram. Exactly 2 LDG.128 per thread, 8 atomics ----
    const int4* __restrict__ row =
        reinterpret_cast<const int4*>(assign + (size_t)b * SEQ);
    const int4 va = row[tid];            // tokens 4*tid   .. 4*tid+3
    const int4 vb = row[tid + THREADS];  // tokens 4096+.. (SEQ/4 = 2*THREADS)

    atomicAdd(&s_hist[va.x >> 1], 1u << ((va.x & 1) << 4));
    atomicAdd(&s_hist[va.y >> 1], 1u << ((va.y & 1) << 4));
    atomicAdd(&s_hist[va.z >> 1], 1u << ((va.z & 1) << 4));
    atomicAdd(&s_hist[va.w >> 1], 1u << ((va.w & 1) << 4));
    atomicAdd(&s_hist[vb.x >> 1], 1u << ((vb.x & 1) << 4));
    atomicAdd(&s_hist[vb.y >> 1], 1u << ((vb.y & 1) << 4));
    atomicAdd(&s_hist[vb.z >> 1], 1u << ((vb.z & 1) << 4));
    atomicAdd(&s_hist[vb.w >> 1], 1u << ((vb.w & 1) << 4));
    __syncthreads();

    // ---- Phase 3: unpack + scale + STG.64 out ----
    // Row sum is exactly SEQ and 1/8192 is a power of two -> exact fp32.
    // Row byte base = b * 201028: base % 8 == 0 for even b, == 4 for odd b.
    float* __restrict__ orow = out + (size_t)b * VOCAB;
    const float inv = 1.0f / (float)SEQ;

    if ((b & 1) == 0) {
        // Aligned pairs (bins 2w, 2w+1) for w in [0, 25128); tail bin 50256.
        float2* __restrict__ o2 = reinterpret_cast<float2*>(orow);
        for (int w = tid; w < WORDS - 1; w += THREADS) {
            const unsigned int c = s_hist[w];
            o2[w] = make_float2((float)(c & 0xFFFFu) * inv,
                                (float)(c >> 16)     * inv);
        }
        if (tid == 0) {
            orow[VOCAB - 1] = (float)(s_hist[WORDS - 1] & 0xFFFFu) * inv;
        }
    } else {
        // Shifted pairs: store (bins 2w+1, 2w+2) = (hi of word w, lo of word
        // w+1) at orow + 1 + 2w, which is 8B-aligned for odd rows. Bin 0 is
        // the scalar head; pairs p in [0, 25128) cover bins 1..50256.
        if (tid == 0) {
            orow[0] = (float)(s_hist[0] & 0xFFFFu) * inv;
        }
        float2* __restrict__ o2 = reinterpret_cast<float2*>(orow + 1);
        for (int w = tid; w < WORDS - 1; w += THREADS) {
            const unsigned int c0 = s_hist[w];
            const unsigned int c1 = s_hist[w + 1];
            o2[w] = make_float2((float)(c0 >> 16)     * inv,
                                (float)(c1 & 0xFFFFu) * inv);
        }
    }
}

extern "C" void kernel_launch(void* const* d_in, const int* in_sizes, int n_in,
                              void* d_out, int out_size) {
    const int* assign = (const int*)d_in[0];   // [batch, SEQ] int32
    float*     out    = (float*)d_out;         // [batch, VOCAB] float32

    const int batch = in_sizes[0] / SEQ;                             // 512
    const size_t smem_bytes = (size_t)WORDS * sizeof(unsigned int);  // 98.2 KB

    cudaFuncSetAttribute(XTermFrequency_hist_kernel,
                         cudaFuncAttributeMaxDynamicSharedMemorySize,
                         (int)smem_bytes);

    XTermFrequency_hist_kernel<<<batch, THREADS, smem_bytes>>>(assign, out);
}

// round 15
// speedup vs baseline: 1.4735x; 1.0556x over previous
#include <cuda_runtime.h>
#include <cstdint>

// assignments [512, 8192] int32 -> frequency [512, 50257] float32.
#define VOCAB      50257
#define SEQ        8192
#define THREADS    512
#define HALF_BINS  25130    // low half bins [0,25130), high half [25130,50257)
#define HALF_WORDS 12565    // packed u16-pair words per half-histogram (50.26 KB)

// Two CTAs per row, split by vocab range (disjoint bins -> no merge needed).
// CTA (2b+h): reads row b, counts only tokens with (v >= HALF_BINS) == h into
// a half-size packed-u16 smem histogram, writes its output slice with STGs.
// Half smem -> 4 CTAs/SM (512 thr each); grid=1024 over 148 SMs = 6.92/SM,
// so wave-quantization tail drops from 15.6% (512-CTA version) to ~1.2%.
// Counts <= 8192 < 2^16 so packed halves never carry; row sum is exactly SEQ
// and 1/8192 is a power of two -> output exact in fp32.
__global__ __launch_bounds__(THREADS, 4)
void XTermFrequency_hist_kernel(const int* __restrict__ assign,
                                float* __restrict__ out) {
    extern __shared__ unsigned int s_hist[];   // HALF_WORDS words

    const int  b   = blockIdx.x >> 1;
    const bool hi  = (blockIdx.x & 1) != 0;
    const int  tid = threadIdx.x;

    // ---- Phase 1: zero half-histogram (uint4 STS, 7 iters/thread) ----
    {
        uint4* __restrict__ s4 = reinterpret_cast<uint4*>(s_hist);
        const uint4 z = make_uint4(0u, 0u, 0u, 0u);
        #pragma unroll
        for (int i = tid; i < HALF_WORDS / 4; i += THREADS) {   // 3141
            s4[i] = z;
        }
        if (tid == 0) {
            s_hist[HALF_WORDS - 1] = 0u;
        }
    }
    __syncthreads();

    // ---- Phase 2: histogram my half. 4 front-batched LDG.128, 16 atomics ----
    const int4* __restrict__ row =
        reinterpret_cast<const int4*>(assign + (size_t)b * SEQ);
    const int4 t0 = row[tid];
    const int4 t1 = row[tid + THREADS];
    const int4 t2 = row[tid + 2 * THREADS];
    const int4 t3 = row[tid + 3 * THREADS];     // SEQ/4 = 2048 = 4*THREADS

    const int base = hi ? HALF_WORDS : 0;
    #define ACC(v)                                                        \
        do {                                                              \
            if (((v) >= HALF_BINS) == hi) {                               \
                atomicAdd(&s_hist[((v) >> 1) - base],                     \
                          1u << (((v) & 1) << 4));                        \
            }                                                             \
        } while (0)
    ACC(t0.x); ACC(t0.y); ACC(t0.z); ACC(t0.w);
    ACC(t1.x); ACC(t1.y); ACC(t1.z); ACC(t1.w);
    ACC(t2.x); ACC(t2.y); ACC(t2.z); ACC(t2.w);
    ACC(t3.x); ACC(t3.y); ACC(t3.z); ACC(t3.w);
    #undef ACC
    __syncthreads();

    // ---- Phase 3: unpack + scale + STG.64 my output slice ----
    // Slice bins [B0, B0+NB). Global float index of B0 = b*50257 + B0;
    // since B0 (0 or 25130) is even, 8B alignment depends only on b parity.
    const int B0 = hi ? HALF_BINS : 0;
    const int NB = hi ? (VOCAB - HALF_BINS) : HALF_BINS;   // 25127 or 25130
    float* __restrict__ orow = out + (size_t)b * VOCAB;
    const float inv = 1.0f / (float)SEQ;

    if ((b & 1) == 0) {
        // Aligned: pair p = (lo, hi) of word p -> bins B0+2p, B0+2p+1.
        float2* __restrict__ o2 = reinterpret_cast<float2*>(orow + B0);
        const int npairs = NB >> 1;
        for (int p = tid; p < npairs; p += THREADS) {
            const unsigned int c = s_hist[p];
            o2[p] = make_float2((float)(c & 0xFFFFu) * inv,
                                (float)(c >> 16)     * inv);
        }
        if ((NB & 1) && tid == 0) {   // odd bin count: last bin = lo of word
            orow[B0 + NB - 1] = (float)(s_hist[(NB - 1) >> 1] & 0xFFFFu) * inv;
        }
    } else {
        // Shifted: head bin B0 scalar, then pair p = (hi of word p,
        // lo of word p+1) at orow + B0 + 1 + 2p (8B-aligned for odd b).
        if (tid == 0) {
            orow[B0] = (float)(s_hist[0] & 0xFFFFu) * inv;
        }
        float2* __restrict__ o2 = reinterpret_cast<float2*>(orow + B0 + 1);
        const int npairs = (NB - 1) >> 1;
        for (int p = tid; p < npairs; p += THREADS) {
            const unsigned int c0 = s_hist[p];
            const unsigned int c1 = s_hist[p + 1];
            o2[p] = make_float2((float)(c0 >> 16)     * inv,
                                (float)(c1 & 0xFFFFu) * inv);
        }
        if (((NB - 1) & 1) && tid == 0) {  // remaining tail = hi of last word
            orow[B0 + NB - 1] = (float)(s_hist[(NB - 1) >> 1] >> 16) * inv;
        }
    }
}

extern "C" void kernel_launch(void* const* d_in, const int* in_sizes, int n_in,
                              void* d_out, int out_size) {
    const int* assign = (const int*)d_in[0];   // [batch, SEQ] int32
    float*     out    = (float*)d_out;         // [batch, VOCAB] float32

    const int batch = in_sizes[0] / SEQ;                                 // 512
    const size_t smem_bytes = (size_t)HALF_WORDS * sizeof(unsigned int); // 50.26 KB

    cudaFuncSetAttribute(XTermFrequency_hist_kernel,
                         cudaFuncAttributeMaxDynamicSharedMemorySize,
                         (int)smem_bytes);

    XTermFrequency_hist_kernel<<<2 * batch, THREADS, smem_bytes>>>(assign, out);
}